// round 15
// baseline (speedup 1.0000x reference)
#include <cuda_runtime.h>
#include <cuda_fp16.h>
#include <cstdint>
#include <cstddef>

// Problem constants
#define BATCH 2
#define SEQ   2048
#define NC    1024
#define NH    16
#define HD    64
#define MROWS (BATCH*SEQ)     // 4096
#define QKVN  (3*NC)          // 3072
#define GK    1024
// q scale folds softmax scale (1/8) and log2(e): logits land in log2 domain
#define QSCALE (0.125f * 1.4426950408889634f)

// Scratch (allocation-free rule: __device__ globals), all fp16
__device__ __half g_q[BATCH*NH*SEQ*HD];     // [b,h,t,d], pre-scaled by QSCALE
__device__ __half g_k[BATCH*NH*SEQ*HD];
__device__ __half g_v[BATCH*NH*SEQ*HD];
__device__ __half g_attn[BATCH*SEQ*NC];     // [b,t,c]
__device__ __half g_x[MROWS*GK];
__device__ __half g_w1[QKVN*GK];
__device__ __half g_w2[NC*GK];

// Dependency flags (zeroed by prep_all each launch)
__device__ uint32_t g_fA[48];   // [nb][b]: bitmask of finished QKV m-blocks
__device__ int      g_fB[32];   // [b*16+bx]: count of finished attn head-blocks

__device__ __forceinline__ uint32_t h2u(__half2 h) {
    return *reinterpret_cast<uint32_t*>(&h);
}
__device__ __forceinline__ float ex2f(float x) {
    float y;
    asm("ex2.approx.ftz.f32 %0, %1;" : "=f"(y) : "f"(x));
    return y;
}
__device__ __forceinline__ uint32_t ldacq(const void* p) {
    uint32_t v;
    asm volatile("ld.acquire.gpu.u32 %0, [%1];" : "=r"(v) : "l"(p) : "memory");
    return v;
}

#define CP16(dst_u32, src_ptr) \
    asm volatile("cp.async.cg.shared.global [%0], [%1], 16;" \
                 :: "r"(dst_u32), "l"(src_ptr) : "memory")
#define CP_COMMIT() asm volatile("cp.async.commit_group;" ::: "memory")
#define CP_WAIT(n)  asm volatile("cp.async.wait_group %0;" :: "n"(n) : "memory")

__device__ __forceinline__ void ldsm4(uint32_t* r, uint32_t a) {
    asm volatile("ldmatrix.sync.aligned.m8n8.x4.shared.b16 {%0,%1,%2,%3}, [%4];"
                 : "=r"(r[0]), "=r"(r[1]), "=r"(r[2]), "=r"(r[3]) : "r"(a));
}
__device__ __forceinline__ void ldsm4t(uint32_t* r, uint32_t a) {
    asm volatile("ldmatrix.sync.aligned.m8n8.x4.trans.shared.b16 {%0,%1,%2,%3}, [%4];"
                 : "=r"(r[0]), "=r"(r[1]), "=r"(r[2]), "=r"(r[3]) : "r"(a));
}
__device__ __forceinline__ void mma16816(float* d, const uint32_t* a,
                                         uint32_t b0, uint32_t b1) {
    asm volatile("mma.sync.aligned.m16n8k16.row.col.f32.f16.f16.f32 "
                 "{%0,%1,%2,%3}, {%4,%5,%6,%7}, {%8,%9}, {%0,%1,%2,%3};"
                 : "+f"(d[0]), "+f"(d[1]), "+f"(d[2]), "+f"(d[3])
                 : "r"(a[0]), "r"(a[1]), "r"(a[2]), "r"(a[3]),
                   "r"(b0), "r"(b1));
}

// ---------------------------------------------------------------------------
// prep: fp32 -> fp16 for x, qkv_w, proj_w; also zero dependency flags.
// Triggers programmatic launch completion early so the fused grid can
// pre-stage its blocks during prep's tail wave.
// ---------------------------------------------------------------------------
#define N8X  (MROWS*GK/8)     // 524288
#define N8W1 (QKVN*GK/8)      // 393216
#define N8W2 (NC*GK/8)        // 131072
__global__ void prep_all(const float4* __restrict__ x,
                         const float4* __restrict__ w1,
                         const float4* __restrict__ w2)
{
    cudaTriggerProgrammaticLaunchCompletion();
    if (blockIdx.x == 0 && threadIdx.x < 80) {
        if (threadIdx.x < 48) g_fA[threadIdx.x] = 0;
        else                  g_fB[threadIdx.x - 48] = 0;
    }
    uint4* dx  = (uint4*)g_x;
    uint4* dw1 = (uint4*)g_w1;
    uint4* dw2 = (uint4*)g_w2;
    for (int i = blockIdx.x * blockDim.x + threadIdx.x;
         i < N8X + N8W1 + N8W2; i += gridDim.x * blockDim.x) {
        const float4* s;
        uint4* d;
        int j;
        if (i < N8X)               { s = x;  d = dx;  j = i; }
        else if (i < N8X + N8W1)   { s = w1; d = dw1; j = i - N8X; }
        else                       { s = w2; d = dw2; j = i - N8X - N8W1; }
        float4 a = s[2 * j], b = s[2 * j + 1];
        uint4 o;
        o.x = h2u(__floats2half2_rn(a.x, a.y));
        o.y = h2u(__floats2half2_rn(a.z, a.w));
        o.z = h2u(__floats2half2_rn(b.x, b.y));
        o.w = h2u(__floats2half2_rn(b.z, b.w));
        d[j] = o;
    }
}

// ---------------------------------------------------------------------------
// GEMM body (raw mma + ldmatrix, R9-proven): 128x128 tile, 256 thr, 8 warps,
// warp 64x32, K-chunk 32, swizzled 64B rows, 4-stage cp.async.
// EPI 1: A=g_x, W=g_w1, scatter q/k/v fp16 (q scaled by QSCALE)
// EPI 2: A=g_attn, W=g_w2, fp32 store + bias
// ---------------------------------------------------------------------------
#define KCH   32
#define STGB  16384
#define CPCH  132
#define FUSED_SMEM 67584

template<int EPI>
__device__ __forceinline__ void gemm_body(char* smc, int m0, int n0,
                                          const float* __restrict__ bias,
                                          float* __restrict__ C)
{
    float* Cs = (float*)smc;
    const uint32_t sbase = (uint32_t)__cvta_generic_to_shared(smc);

    const __half* __restrict__ A = (EPI == 1) ? g_x  : g_attn;
    const __half* __restrict__ W = (EPI == 1) ? g_w1 : g_w2;
    const int N = (EPI == 1) ? QKVN : NC;

    const int tid  = threadIdx.x;
    const int lane = tid & 31;
    const int wid  = tid >> 5;
    const int wm = wid >> 2;
    const int wn = wid & 3;

    float acc[4][4][4];
#pragma unroll
    for (int im = 0; im < 4; im++)
#pragma unroll
        for (int jn = 0; jn < 4; jn++)
#pragma unroll
            for (int c = 0; c < 4; c++) acc[im][jn][c] = 0.f;

#define GISSUE(ch) do {                                                       \
        uint32_t _st = sbase + (uint32_t)(((ch) & 3) * STGB);                 \
        int _k0 = (ch) * KCH;                                                 \
        _Pragma("unroll")                                                     \
        for (int _j = 0; _j < 4; _j++) {                                      \
            int _idx = tid + _j * 256;                                        \
            int _r = (_idx & 511) >> 2, _s = _idx & 3;                        \
            int _p = _s ^ ((_r >> 1) & 3);                                    \
            if (_idx < 512)                                                   \
                CP16(_st + (uint32_t)(_r * 64 + _p * 16),                     \
                     A + (size_t)(m0 + _r) * GK + _k0 + _s * 8);              \
            else                                                              \
                CP16(_st + 8192u + (uint32_t)(_r * 64 + _p * 16),             \
                     W + (size_t)(n0 + _r) * GK + _k0 + _s * 8);              \
        }                                                                     \
    } while (0)

    GISSUE(0); CP_COMMIT();
    GISSUE(1); CP_COMMIT();
    GISSUE(2); CP_COMMIT();

    const int lr = lane & 15;
    const int lh = lane >> 4;

    constexpr int NCH = GK / KCH;
    for (int i = 0; i < NCH; i++) {
        CP_WAIT(2);
        __syncthreads();
        if (i + 3 < NCH) GISSUE(i + 3);
        CP_COMMIT();

        const uint32_t ab = sbase + (uint32_t)((i & 3) * STGB);
        const uint32_t bb = ab + 8192u;

#pragma unroll
        for (int dk = 0; dk < 2; dk++) {
            const int seg = dk * 2 + lh;
            uint32_t bf[2][4];
#pragma unroll
            for (int jn2 = 0; jn2 < 2; jn2++) {
                int row = wn * 32 + jn2 * 16 + lr;
                int p = seg ^ ((row >> 1) & 3);
                ldsm4(bf[jn2], bb + (uint32_t)(row * 64 + p * 16));
            }
#pragma unroll
            for (int im = 0; im < 4; im++) {
                uint32_t af[4];
                int row = wm * 64 + im * 16 + lr;
                int p = seg ^ ((row >> 1) & 3);
                ldsm4(af, ab + (uint32_t)(row * 64 + p * 16));
                mma16816(acc[im][0], af, bf[0][0], bf[0][2]);
                mma16816(acc[im][1], af, bf[0][1], bf[0][3]);
                mma16816(acc[im][2], af, bf[1][0], bf[1][2]);
                mma16816(acc[im][3], af, bf[1][1], bf[1][3]);
            }
        }
    }
#undef GISSUE
    __syncthreads();

    const int rsub = lane >> 2;
    const int csub = 2 * (lane & 3);
#pragma unroll
    for (int im = 0; im < 4; im++) {
        const int r0 = wm * 64 + im * 16 + rsub;
#pragma unroll
        for (int jn = 0; jn < 4; jn++) {
            const int c0 = wn * 32 + jn * 8 + csub;
            *(float2*)(Cs + r0 * CPCH + c0) =
                make_float2(acc[im][jn][0], acc[im][jn][1]);
            *(float2*)(Cs + (r0 + 8) * CPCH + c0) =
                make_float2(acc[im][jn][2], acc[im][jn][3]);
        }
    }
    __syncthreads();

#pragma unroll
    for (int l = 0; l < 16; l++) {
        int idx = tid + l * 256;
        int row = idx >> 5;
        int col = (idx & 31) * 4;
        float4 v  = *(float4*)(Cs + row * CPCH + col);
        float4 bb = *(const float4*)(bias + n0 + col);
        v.x += bb.x; v.y += bb.y; v.z += bb.z; v.w += bb.w;
        int m = m0 + row;
        if (EPI == 1) {
            int n = n0 + col;
            int kind = n >> 10;
            int c = n & 1023;
            int h = c >> 6;
            int d = c & 63;
            if (kind == 0) {
                v.x *= QSCALE; v.y *= QSCALE; v.z *= QSCALE; v.w *= QSCALE;
            }
            __half* buf = (kind == 0) ? g_q : (kind == 1) ? g_k : g_v;
            int b = m >> 11;
            int t = m & 2047;
            uint2 u;
            u.x = h2u(__floats2half2_rn(v.x, v.y));
            u.y = h2u(__floats2half2_rn(v.z, v.w));
            *(uint2*)(buf + ((size_t)((b * NH + h) * SEQ + t)) * HD + d) = u;
        } else {
            *(float4*)(C + (size_t)m * N + n0 + col) = v;
        }
    }
}

// ---------------------------------------------------------------------------
// Attention body (R9-proven): 256 threads, 8 warps (warp = 16 q-rows),
// q-tile 128, kv-tile 64, double-buffered cp.async. Register-resident S->P,
// no max-subtraction, ex2 in log2 domain.
// ---------------------------------------------------------------------------
#define AHP    72
#define KVSTG  18432
#define OFF_KV 18432

__device__ __forceinline__ void attn_body(char* smc, int a)
{
    __half* Ps = (__half*)smc;
    const uint32_t sbase = (uint32_t)__cvta_generic_to_shared(smc);

    const int tid  = threadIdx.x;
    const int lane = tid & 31;
    const int wid  = tid >> 5;

    const int pp = a >> 6;             // head pair 0..7
    const int s  = a & 63;             // heavy-first within pair
    const int bx = 15 - (s >> 2);
    const int b  = s & 1;
    const int h  = pp * 2 + ((s >> 1) & 1);
    const int bh = b * 16 + h;
    const int tq0 = bx * 128;
    const int ntiles = 2 * bx + 2;

    // Wait for q tile bx and full k/v prefix of this (head, batch).
    if (tid == 0) {
        const uint32_t need = (1u << (bx + 1)) - 1u;
        while (true) {
            uint32_t fq = ldacq(&g_fA[pp * 2 + b]);
            uint32_t fk = ldacq(&g_fA[(8 + pp) * 2 + b]);
            uint32_t fv = ldacq(&g_fA[(16 + pp) * 2 + b]);
            if (((fq >> bx) & 1u) && (fk & need) == need && (fv & need) == need)
                break;
            __nanosleep(128);
        }
    }
    __syncthreads();

    const __half* Qg = g_q + (size_t)bh * SEQ * HD;
    const __half* Kg = g_k + (size_t)bh * SEQ * HD;
    const __half* Vg = g_v + (size_t)bh * SEQ * HD;

    // Q copy: 1024 x 16B chunks
#pragma unroll
    for (int j = 0; j < 4; j++) {
        int idx = tid + j * 256;
        int r = idx >> 3, g = idx & 7;
        CP16(sbase + (uint32_t)((r * AHP + g * 8) * 2),
             Qg + (size_t)(tq0 + r) * HD + g * 8);
    }
#define ISSUE_KV(tile) do {                                                   \
        int _s = (tile) & 1;                                                  \
        int _k0 = (tile) * 64;                                                \
        uint32_t _kb = sbase + OFF_KV + (uint32_t)_s * KVSTG;                 \
        _Pragma("unroll")                                                     \
        for (int _j = 0; _j < 2; _j++) {                                      \
            int _idx = tid + _j * 256;                                        \
            int _r = _idx >> 3, _g = _idx & 7;                                \
            CP16(_kb + (uint32_t)((_r * AHP + _g * 8) * 2),                   \
                 Kg + (size_t)(_k0 + _r) * HD + _g * 8);                      \
            CP16(_kb + 9216u + (uint32_t)((_r * AHP + _g * 8) * 2),           \
                 Vg + (size_t)(_k0 + _r) * HD + _g * 8);                      \
        }                                                                     \
    } while (0)

    ISSUE_KV(0); CP_COMMIT();
    ISSUE_KV(1); CP_COMMIT();

    uint32_t qf[4][4];
    float of[8][4];
    float rs[2] = {0.f, 0.f};
#pragma unroll
    for (int jn = 0; jn < 8; jn++)
#pragma unroll
        for (int c = 0; c < 4; c++) of[jn][c] = 0.f;

    const int g8  = lane >> 3;
    const int li  = lane & 7;
    const int rsub = lane >> 2;

    for (int i = 0; i < ntiles; i++) {
        CP_WAIT(1);
        __syncthreads();
        const uint32_t kb = sbase + OFF_KV + (uint32_t)(i & 1) * KVSTG;
        const uint32_t vb = kb + 9216u;

        if (i == 0) {
#pragma unroll
            for (int dk = 0; dk < 4; dk++) {
                uint32_t qa = sbase + (uint32_t)(((wid * 16 + (lane & 15)) * AHP
                               + dk * 16 + (lane >> 4) * 8) * 2);
                ldsm4(qf[dk], qa);
            }
        }

        const int kt0 = i * 64;
        const bool msk = (i >= ntiles - 2);
        uint32_t pa[4][4];

#pragma unroll
        for (int jnp = 0; jnp < 4; jnp++) {
            float sc[2][4];
#pragma unroll
            for (int jh = 0; jh < 2; jh++)
#pragma unroll
                for (int c = 0; c < 4; c++) sc[jh][c] = 0.f;

#pragma unroll
            for (int dk = 0; dk < 4; dk++) {
                uint32_t kf[4];
                uint32_t ka = kb + (uint32_t)(((jnp * 16 + (g8 >> 1) * 8 + li) * AHP
                               + dk * 16 + (g8 & 1) * 8) * 2);
                ldsm4(kf, ka);
                mma16816(sc[0], qf[dk], kf[0], kf[1]);
                mma16816(sc[1], qf[dk], kf[2], kf[3]);
            }
            const int rr0 = tq0 + wid * 16 + rsub;
            const int rr1 = rr0 + 8;
#pragma unroll
            for (int jh = 0; jh < 2; jh++) {
                const int cb = kt0 + jnp * 16 + jh * 8 + 2 * (lane & 3);
                float p0 = ex2f(sc[jh][0]);
                float p1 = ex2f(sc[jh][1]);
                float p2 = ex2f(sc[jh][2]);
                float p3 = ex2f(sc[jh][3]);
                if (msk) {
                    if (cb     > rr0) p0 = 0.f;
                    if (cb + 1 > rr0) p1 = 0.f;
                    if (cb     > rr1) p2 = 0.f;
                    if (cb + 1 > rr1) p3 = 0.f;
                }
                rs[0] += p0 + p1;
                rs[1] += p2 + p3;
                pa[jnp][jh * 2 + 0] = h2u(__floats2half2_rn(p0, p1));
                pa[jnp][jh * 2 + 1] = h2u(__floats2half2_rn(p2, p3));
            }
        }

#pragma unroll
        for (int kk = 0; kk < 4; kk++) {
#pragma unroll
            for (int j2 = 0; j2 < 4; j2++) {
                uint32_t vf[4];
                uint32_t va = vb + (uint32_t)(((kk * 16 + (g8 & 1) * 8 + li) * AHP
                               + j2 * 16 + (g8 >> 1) * 8) * 2);
                ldsm4t(vf, va);
                mma16816(of[2 * j2],     pa[kk], vf[0], vf[1]);
                mma16816(of[2 * j2 + 1], pa[kk], vf[2], vf[3]);
            }
        }
        __syncthreads();
        if (i + 2 < ntiles) ISSUE_KV(i + 2);
        CP_COMMIT();
    }
#undef ISSUE_KV

    float v0 = rs[0], v1 = rs[1];
    v0 += __shfl_xor_sync(0xffffffff, v0, 1);
    v0 += __shfl_xor_sync(0xffffffff, v0, 2);
    v1 += __shfl_xor_sync(0xffffffff, v1, 1);
    v1 += __shfl_xor_sync(0xffffffff, v1, 2);
    const float inv0 = 1.0f / v0;
    const float inv1 = 1.0f / v1;

    const int r0 = wid * 16 + rsub;
#pragma unroll
    for (int jn = 0; jn < 8; jn++) {
        const int col = jn * 8 + 2 * (lane & 3);
        *(__half2*)(Ps + r0 * AHP + col) =
            __floats2half2_rn(of[jn][0] * inv0, of[jn][1] * inv0);
        *(__half2*)(Ps + (r0 + 8) * AHP + col) =
            __floats2half2_rn(of[jn][2] * inv1, of[jn][3] * inv1);
    }
    __syncthreads();

#pragma unroll
    for (int j = 0; j < 4; j++) {
        int chunk = tid + j * 256;
        int row = chunk >> 3, seg = chunk & 7;
        uint4 v = *(uint4*)(Ps + row * AHP + seg * 8);
        *(uint4*)(g_attn + (size_t)(b * SEQ + tq0 + row) * NC + h * HD + seg * 8) = v;
    }

    __threadfence();
    __syncthreads();
    if (tid == 0) atomicAdd(&g_fB[b * 16 + bx], 1);
}

// ---------------------------------------------------------------------------
// Fused kernel (R9 schedule): 768 QKV tiles | 512 attn blocks | 256 proj.
// QKV pp-major; attn pp-major heavy-first; proj m-block ascending.
// Launched with programmatic dependency on prep_all: blocks pre-stage during
// prep's tail, then gridDepSync guarantees converted data + flag visibility.
// ---------------------------------------------------------------------------
__global__ __launch_bounds__(256, 2) void fused(
    const float* __restrict__ qkv_b,
    const float* __restrict__ proj_b,
    float* __restrict__ out)
{
    cudaGridDependencySynchronize();

    extern __shared__ char smc[];
    const int bid = blockIdx.x;

    if (bid < 768) {
        // QKV: pp-major; within pair: (q,k,v) x m-blocks (batches interleaved)
        const int pp   = bid / 96;
        const int r    = bid % 96;
        const int kind = r % 3;
        const int mbs  = r / 3;
        const int nb   = pp + kind * 8;
        const int mb   = (mbs >> 1) | ((mbs & 1) << 4);
        gemm_body<1>(smc, mb * 128, nb * 128, qkv_b, nullptr);
        __threadfence();
        __syncthreads();
        if (threadIdx.x == 0)
            atomicOr(&g_fA[nb * 2 + (mb >> 4)], 1u << (mb & 15));
    } else if (bid < 1280) {
        attn_body(smc, bid - 768);
    } else {
        const int c  = bid - 1280;
        const int mb = c >> 3;          // m-block ascending: early rows first
        const int nb = c & 7;
        if (threadIdx.x == 0) {
            while ((int)ldacq(&g_fB[mb]) < 16) __nanosleep(256);
        }
        __syncthreads();
        gemm_body<2>(smc, mb * 128, nb * 128, proj_b, out);
    }
}

// ---------------------------------------------------------------------------
// kernel_launch
// ---------------------------------------------------------------------------
extern "C" void kernel_launch(void* const* d_in, const int* in_sizes, int n_in,
                              void* d_out, int out_size)
{
    const float* x      = (const float*)d_in[0];
    const float* qkv_w  = (const float*)d_in[1];
    const float* qkv_b  = (const float*)d_in[2];
    const float* proj_w = (const float*)d_in[3];
    const float* proj_b = (const float*)d_in[4];
    float* out = (float*)d_out;

    cudaFuncSetAttribute(fused,
                         cudaFuncAttributeMaxDynamicSharedMemorySize, FUSED_SMEM);

    // 0) fp32 -> fp16 conversion + flag reset (triggers PDL early)
    prep_all<<<1184, 256>>>((const float4*)x, (const float4*)qkv_w,
                            (const float4*)proj_w);

    // 1-3) Fused QKV + attention + projection, programmatic dependent launch
    cudaLaunchConfig_t cfg = {};
    cfg.gridDim = dim3(1536, 1, 1);
    cfg.blockDim = dim3(256, 1, 1);
    cfg.dynamicSmemBytes = FUSED_SMEM;
    cfg.stream = 0;
    cudaLaunchAttribute attrs[1];
    attrs[0].id = cudaLaunchAttributeProgrammaticStreamSerialization;
    attrs[0].val.programmaticStreamSerializationAllowed = 1;
    cfg.attrs = attrs;
    cfg.numAttrs = 1;
    cudaLaunchKernelEx(&cfg, fused, qkv_b, proj_b, out);
}

// round 16
// speedup vs baseline: 1.0233x; 1.0233x over previous
#include <cuda_runtime.h>
#include <cuda_fp16.h>
#include <cstdint>
#include <cstddef>

// Problem constants
#define BATCH 2
#define SEQ   2048
#define NC    1024
#define NH    16
#define HD    64
#define MROWS (BATCH*SEQ)     // 4096
#define QKVN  (3*NC)          // 3072
#define GK    1024
// q scale folds softmax scale (1/8) and log2(e): logits land in log2 domain
#define QSCALE (0.125f * 1.4426950408889634f)

// Scratch (allocation-free rule: __device__ globals), all fp16
__device__ __half g_q[BATCH*NH*SEQ*HD];     // [b,h,t,d], pre-scaled by QSCALE
__device__ __half g_k[BATCH*NH*SEQ*HD];
__device__ __half g_v[BATCH*NH*SEQ*HD];
__device__ __half g_attn[BATCH*SEQ*NC];     // [b,t,c]
__device__ __half g_x[MROWS*GK];
__device__ __half g_w1[QKVN*GK];
__device__ __half g_w2[NC*GK];

// Dependency flags (zeroed by prep_all each launch)
__device__ uint32_t g_fA[48];   // [nb][b]: bitmask of finished QKV m-blocks
__device__ int      g_fB[32];   // [b*16+bx]: count of finished attn head-blocks

__device__ __forceinline__ uint32_t h2u(__half2 h) {
    return *reinterpret_cast<uint32_t*>(&h);
}
__device__ __forceinline__ float ex2f(float x) {
    float y;
    asm("ex2.approx.ftz.f32 %0, %1;" : "=f"(y) : "f"(x));
    return y;
}
__device__ __forceinline__ uint32_t ldacq(const void* p) {
    uint32_t v;
    asm volatile("ld.acquire.gpu.u32 %0, [%1];" : "=r"(v) : "l"(p) : "memory");
    return v;
}

#define CP16(dst_u32, src_ptr) \
    asm volatile("cp.async.cg.shared.global [%0], [%1], 16;" \
                 :: "r"(dst_u32), "l"(src_ptr) : "memory")
#define CP_COMMIT() asm volatile("cp.async.commit_group;" ::: "memory")
#define CP_WAIT(n)  asm volatile("cp.async.wait_group %0;" :: "n"(n) : "memory")

__device__ __forceinline__ void ldsm4(uint32_t* r, uint32_t a) {
    asm volatile("ldmatrix.sync.aligned.m8n8.x4.shared.b16 {%0,%1,%2,%3}, [%4];"
                 : "=r"(r[0]), "=r"(r[1]), "=r"(r[2]), "=r"(r[3]) : "r"(a));
}
__device__ __forceinline__ void ldsm4t(uint32_t* r, uint32_t a) {
    asm volatile("ldmatrix.sync.aligned.m8n8.x4.trans.shared.b16 {%0,%1,%2,%3}, [%4];"
                 : "=r"(r[0]), "=r"(r[1]), "=r"(r[2]), "=r"(r[3]) : "r"(a));
}
__device__ __forceinline__ void mma16816(float* d, const uint32_t* a,
                                         uint32_t b0, uint32_t b1) {
    asm volatile("mma.sync.aligned.m16n8k16.row.col.f32.f16.f16.f32 "
                 "{%0,%1,%2,%3}, {%4,%5,%6,%7}, {%8,%9}, {%0,%1,%2,%3};"
                 : "+f"(d[0]), "+f"(d[1]), "+f"(d[2]), "+f"(d[3])
                 : "r"(a[0]), "r"(a[1]), "r"(a[2]), "r"(a[3]),
                   "r"(b0), "r"(b1));
}

// ---------------------------------------------------------------------------
// prep: fp32 -> fp16 for x, qkv_w, proj_w; also zero dependency flags.
// ---------------------------------------------------------------------------
#define N8X  (MROWS*GK/8)     // 524288
#define N8W1 (QKVN*GK/8)      // 393216
#define N8W2 (NC*GK/8)        // 131072
__global__ void prep_all(const float4* __restrict__ x,
                         const float4* __restrict__ w1,
                         const float4* __restrict__ w2)
{
    if (blockIdx.x == 0 && threadIdx.x < 80) {
        if (threadIdx.x < 48) g_fA[threadIdx.x] = 0;
        else                  g_fB[threadIdx.x - 48] = 0;
    }
    uint4* dx  = (uint4*)g_x;
    uint4* dw1 = (uint4*)g_w1;
    uint4* dw2 = (uint4*)g_w2;
    for (int i = blockIdx.x * blockDim.x + threadIdx.x;
         i < N8X + N8W1 + N8W2; i += gridDim.x * blockDim.x) {
        const float4* s;
        uint4* d;
        int j;
        if (i < N8X)               { s = x;  d = dx;  j = i; }
        else if (i < N8X + N8W1)   { s = w1; d = dw1; j = i - N8X; }
        else                       { s = w2; d = dw2; j = i - N8X - N8W1; }
        float4 a = s[2 * j], b = s[2 * j + 1];
        uint4 o;
        o.x = h2u(__floats2half2_rn(a.x, a.y));
        o.y = h2u(__floats2half2_rn(a.z, a.w));
        o.z = h2u(__floats2half2_rn(b.x, b.y));
        o.w = h2u(__floats2half2_rn(b.z, b.w));
        d[j] = o;
    }
}

// ---------------------------------------------------------------------------
// GEMM body, 128 threads: 128x128 tile, 4 warps in 2x2, warp tile 64x64.
// K-chunk 32, swizzled 64B rows, 4-stage cp.async. 32 MMAs per 8 ldsm.
// EPI 1: A=g_x, W=g_w1, scatter q/k/v fp16 (q scaled by QSCALE)
// EPI 2: A=g_attn, W=g_w2, fp32 store + bias
// ---------------------------------------------------------------------------
#define KCH   32
#define STGB  16384
#define CPCH  132
#define FUSED_SMEM 67584

template<int EPI>
__device__ __forceinline__ void gemm_body(char* smc, int m0, int n0,
                                          const float* __restrict__ bias,
                                          float* __restrict__ C)
{
    float* Cs = (float*)smc;
    const uint32_t sbase = (uint32_t)__cvta_generic_to_shared(smc);

    const __half* __restrict__ A = (EPI == 1) ? g_x  : g_attn;
    const __half* __restrict__ W = (EPI == 1) ? g_w1 : g_w2;
    const int N = (EPI == 1) ? QKVN : NC;

    const int tid  = threadIdx.x;
    const int lane = tid & 31;
    const int wid  = tid >> 5;        // 0..3
    const int wm = wid >> 1;          // 0..1 (64-row slab)
    const int wn = wid & 1;           // 0..1 (64-col slab)

    float acc[4][8][4];               // [im][jn(8 x n8)][c]
#pragma unroll
    for (int im = 0; im < 4; im++)
#pragma unroll
        for (int jn = 0; jn < 8; jn++)
#pragma unroll
            for (int c = 0; c < 4; c++) acc[im][jn][c] = 0.f;

    // 1024 16B chunks per stage: idx<512 -> A (r=idx>>2, s=idx&3), else W.
#define GISSUE(ch) do {                                                       \
        uint32_t _st = sbase + (uint32_t)(((ch) & 3) * STGB);                 \
        int _k0 = (ch) * KCH;                                                 \
        _Pragma("unroll")                                                     \
        for (int _j = 0; _j < 8; _j++) {                                      \
            int _idx = tid + _j * 128;                                        \
            int _r = (_idx & 511) >> 2, _s = _idx & 3;                        \
            int _p = _s ^ ((_r >> 1) & 3);                                    \
            if (_idx < 512)                                                   \
                CP16(_st + (uint32_t)(_r * 64 + _p * 16),                     \
                     A + (size_t)(m0 + _r) * GK + _k0 + _s * 8);              \
            else                                                              \
                CP16(_st + 8192u + (uint32_t)(_r * 64 + _p * 16),             \
                     W + (size_t)(n0 + _r) * GK + _k0 + _s * 8);              \
        }                                                                     \
    } while (0)

    GISSUE(0); CP_COMMIT();
    GISSUE(1); CP_COMMIT();
    GISSUE(2); CP_COMMIT();

    const int lr = lane & 15;
    const int lh = lane >> 4;

    constexpr int NCH = GK / KCH;     // 32
    for (int i = 0; i < NCH; i++) {
        CP_WAIT(2);
        __syncthreads();
        if (i + 3 < NCH) GISSUE(i + 3);
        CP_COMMIT();

        const uint32_t ab = sbase + (uint32_t)((i & 3) * STGB);
        const uint32_t bb = ab + 8192u;

#pragma unroll
        for (int dk = 0; dk < 2; dk++) {
            const int seg = dk * 2 + lh;
            uint32_t bf[4][4];
#pragma unroll
            for (int jn2 = 0; jn2 < 4; jn2++) {
                int row = wn * 64 + jn2 * 16 + lr;
                int p = seg ^ ((row >> 1) & 3);
                ldsm4(bf[jn2], bb + (uint32_t)(row * 64 + p * 16));
            }
#pragma unroll
            for (int im = 0; im < 4; im++) {
                uint32_t af[4];
                int row = wm * 64 + im * 16 + lr;
                int p = seg ^ ((row >> 1) & 3);
                ldsm4(af, ab + (uint32_t)(row * 64 + p * 16));
                // B frag order per ldsm: [0]=(n0-7,k0-7) [1]=(n8-15,k0-7)
                //                        [2]=(n0-7,k8-15) [3]=(n8-15,k8-15)
#pragma unroll
                for (int jn2 = 0; jn2 < 4; jn2++) {
                    mma16816(acc[im][jn2 * 2 + 0], af, bf[jn2][0], bf[jn2][2]);
                    mma16816(acc[im][jn2 * 2 + 1], af, bf[jn2][1], bf[jn2][3]);
                }
            }
        }
    }
#undef GISSUE
    __syncthreads();

    // Epilogue: acc frags -> smem (fp32, m16n8 layout) -> bias/scatter
    const int rsub = lane >> 2;
    const int csub = 2 * (lane & 3);
#pragma unroll
    for (int im = 0; im < 4; im++) {
        const int r0 = wm * 64 + im * 16 + rsub;
#pragma unroll
        for (int jn = 0; jn < 8; jn++) {
            const int c0 = wn * 64 + jn * 8 + csub;
            *(float2*)(Cs + r0 * CPCH + c0) =
                make_float2(acc[im][jn][0], acc[im][jn][1]);
            *(float2*)(Cs + (r0 + 8) * CPCH + c0) =
                make_float2(acc[im][jn][2], acc[im][jn][3]);
        }
    }
    __syncthreads();

#pragma unroll
    for (int l = 0; l < 32; l++) {
        int idx = tid + l * 128;
        int row = idx >> 5;
        int col = (idx & 31) * 4;
        float4 v  = *(float4*)(Cs + row * CPCH + col);
        float4 bb = *(const float4*)(bias + n0 + col);
        v.x += bb.x; v.y += bb.y; v.z += bb.z; v.w += bb.w;
        int m = m0 + row;
        if (EPI == 1) {
            int n = n0 + col;
            int kind = n >> 10;
            int c = n & 1023;
            int h = c >> 6;
            int d = c & 63;
            if (kind == 0) {
                v.x *= QSCALE; v.y *= QSCALE; v.z *= QSCALE; v.w *= QSCALE;
            }
            __half* buf = (kind == 0) ? g_q : (kind == 1) ? g_k : g_v;
            int b = m >> 11;
            int t = m & 2047;
            uint2 u;
            u.x = h2u(__floats2half2_rn(v.x, v.y));
            u.y = h2u(__floats2half2_rn(v.z, v.w));
            *(uint2*)(buf + ((size_t)((b * NH + h) * SEQ + t)) * HD + d) = u;
        } else {
            *(float4*)(C + (size_t)m * N + n0 + col) = v;
        }
    }
}

// ---------------------------------------------------------------------------
// Attention body: 128 threads, 4 warps (warp = 32 q-rows), q-tile 128,
// kv-tile 64, double-buffered cp.async (R8-proven layout and pairing).
// Register-resident S->P (FA2 layout identity), no max-subtraction,
// ex2 in log2 domain. Flags as in R9.
// ---------------------------------------------------------------------------
#define AHP    72
#define KVSTG  18432
#define OFF_KV 18432

__device__ __forceinline__ void attn_body(char* smc, int a)
{
    __half* Ps = (__half*)smc;
    const uint32_t sbase = (uint32_t)__cvta_generic_to_shared(smc);

    const int tid  = threadIdx.x;
    const int lane = tid & 31;
    const int wid  = tid >> 5;

    const int pp = a >> 6;             // head pair 0..7
    const int s  = a & 63;             // heavy-first within pair
    const int bx = 15 - (s >> 2);
    const int b  = s & 1;
    const int h  = pp * 2 + ((s >> 1) & 1);
    const int bh = b * 16 + h;
    const int tq0 = bx * 128;
    const int ntiles = 2 * bx + 2;

    // Wait for q tile bx and full k/v prefix of this (head, batch).
    if (tid == 0) {
        const uint32_t need = (1u << (bx + 1)) - 1u;
        while (true) {
            uint32_t fq = ldacq(&g_fA[pp * 2 + b]);
            uint32_t fk = ldacq(&g_fA[(8 + pp) * 2 + b]);
            uint32_t fv = ldacq(&g_fA[(16 + pp) * 2 + b]);
            if (((fq >> bx) & 1u) && (fk & need) == need && (fv & need) == need)
                break;
            __nanosleep(128);
        }
    }
    __syncthreads();

    const __half* Qg = g_q + (size_t)bh * SEQ * HD;
    const __half* Kg = g_k + (size_t)bh * SEQ * HD;
    const __half* Vg = g_v + (size_t)bh * SEQ * HD;

    // Q: 128 rows x 8 chunks of 16B
#pragma unroll
    for (int j = 0; j < 8; j++) {
        int idx = tid + j * 128;
        int r = idx >> 3, g = idx & 7;
        CP16(sbase + (uint32_t)((r * AHP + g * 8) * 2),
             Qg + (size_t)(tq0 + r) * HD + g * 8);
    }
#define ISSUE_KV(tile) do {                                                   \
        int _s = (tile) & 1;                                                  \
        int _k0 = (tile) * 64;                                                \
        uint32_t _kb = sbase + OFF_KV + (uint32_t)_s * KVSTG;                 \
        _Pragma("unroll")                                                     \
        for (int _j = 0; _j < 4; _j++) {                                      \
            int _idx = tid + _j * 128;                                        \
            int _r = _idx >> 3, _g = _idx & 7;                                \
            CP16(_kb + (uint32_t)((_r * AHP + _g * 8) * 2),                   \
                 Kg + (size_t)(_k0 + _r) * HD + _g * 8);                      \
            CP16(_kb + 9216u + (uint32_t)((_r * AHP + _g * 8) * 2),           \
                 Vg + (size_t)(_k0 + _r) * HD + _g * 8);                      \
        }                                                                     \
    } while (0)

    ISSUE_KV(0); CP_COMMIT();      // group 0: Q + KV0
    ISSUE_KV(1); CP_COMMIT();

    uint32_t qf[2][4][4];          // [im][dk] A-frags, persistent
    float of[2][8][4];             // [im][jn] O accumulators
    float rs[2][2] = {{0.f, 0.f}, {0.f, 0.f}};
#pragma unroll
    for (int im = 0; im < 2; im++)
#pragma unroll
        for (int jn = 0; jn < 8; jn++)
#pragma unroll
            for (int c = 0; c < 4; c++) of[im][jn][c] = 0.f;

    const int g8  = lane >> 3;      // ldmatrix address group
    const int li  = lane & 7;
    const int rsub = lane >> 2;     // acc row within 16-block

    for (int i = 0; i < ntiles; i++) {
        CP_WAIT(1);
        __syncthreads();
        const uint32_t kb = sbase + OFF_KV + (uint32_t)(i & 1) * KVSTG;
        const uint32_t vb = kb + 9216u;

        if (i == 0) {
#pragma unroll
            for (int im = 0; im < 2; im++)
#pragma unroll
                for (int dk = 0; dk < 4; dk++) {
                    uint32_t qa = sbase + (uint32_t)(((wid * 32 + im * 16 + (lane & 15)) * AHP
                                   + dk * 16 + (lane >> 4) * 8) * 2);
                    ldsm4(qf[im][dk], qa);
                }
        }

        const int kt0 = i * 64;
        const bool msk = (i >= ntiles - 2);
        uint32_t pa[2][4][4];       // P as A-frags: [im][kk]

#pragma unroll
        for (int jnp = 0; jnp < 4; jnp++) {
            float sc[2][2][4];
#pragma unroll
            for (int im = 0; im < 2; im++)
#pragma unroll
                for (int jh = 0; jh < 2; jh++)
#pragma unroll
                    for (int c = 0; c < 4; c++) sc[im][jh][c] = 0.f;

#pragma unroll
            for (int dk = 0; dk < 4; dk++) {
                uint32_t kf[4];
                // groups: n-block = g8>>1, k-block = g8&1
                uint32_t ka = kb + (uint32_t)(((jnp * 16 + (g8 >> 1) * 8 + li) * AHP
                               + dk * 16 + (g8 & 1) * 8) * 2);
                ldsm4(kf, ka);
                mma16816(sc[0][0], qf[0][dk], kf[0], kf[1]);
                mma16816(sc[0][1], qf[0][dk], kf[2], kf[3]);
                mma16816(sc[1][0], qf[1][dk], kf[0], kf[1]);
                mma16816(sc[1][1], qf[1][dk], kf[2], kf[3]);
            }
            // exp2 + mask + pack to fp16 A-frags + row sums (all in regs)
#pragma unroll
            for (int im = 0; im < 2; im++) {
                const int rr0 = tq0 + wid * 32 + im * 16 + rsub;
                const int rr1 = rr0 + 8;
#pragma unroll
                for (int jh = 0; jh < 2; jh++) {
                    const int cb = kt0 + jnp * 16 + jh * 8 + 2 * (lane & 3);
                    float p0 = ex2f(sc[im][jh][0]);
                    float p1 = ex2f(sc[im][jh][1]);
                    float p2 = ex2f(sc[im][jh][2]);
                    float p3 = ex2f(sc[im][jh][3]);
                    if (msk) {
                        if (cb     > rr0) p0 = 0.f;
                        if (cb + 1 > rr0) p1 = 0.f;
                        if (cb     > rr1) p2 = 0.f;
                        if (cb + 1 > rr1) p3 = 0.f;
                    }
                    rs[im][0] += p0 + p1;
                    rs[im][1] += p2 + p3;
                    pa[im][jnp][jh * 2 + 0] = h2u(__floats2half2_rn(p0, p1));
                    pa[im][jnp][jh * 2 + 1] = h2u(__floats2half2_rn(p2, p3));
                }
            }
        }

        // O += P V
#pragma unroll
        for (int kk = 0; kk < 4; kk++) {
#pragma unroll
            for (int j2 = 0; j2 < 4; j2++) {
                uint32_t vf[4];
                // groups: k-block = g8&1, n-block = g8>>1 (trans load)
                uint32_t va = vb + (uint32_t)(((kk * 16 + (g8 & 1) * 8 + li) * AHP
                               + j2 * 16 + (g8 >> 1) * 8) * 2);
                ldsm4t(vf, va);
                mma16816(of[0][2 * j2],     pa[0][kk], vf[0], vf[1]);
                mma16816(of[1][2 * j2],     pa[1][kk], vf[0], vf[1]);
                mma16816(of[0][2 * j2 + 1], pa[0][kk], vf[2], vf[3]);
                mma16816(of[1][2 * j2 + 1], pa[1][kk], vf[2], vf[3]);
            }
        }
        __syncthreads();
        if (i + 2 < ntiles) ISSUE_KV(i + 2);
        CP_COMMIT();
    }
#undef ISSUE_KV

    // Row-sum reduce across the 4 lanes sharing each row, invert.
    float inv[2][2];
#pragma unroll
    for (int im = 0; im < 2; im++)
#pragma unroll
        for (int jr = 0; jr < 2; jr++) {
            float v = rs[im][jr];
            v += __shfl_xor_sync(0xffffffff, v, 1);
            v += __shfl_xor_sync(0xffffffff, v, 2);
            inv[im][jr] = 1.0f / v;
        }

    // Normalize + stage O to smem (fp16), then coalesced copy to g_attn.
#pragma unroll
    for (int im = 0; im < 2; im++) {
        const int r0 = wid * 32 + im * 16 + rsub;
#pragma unroll
        for (int jn = 0; jn < 8; jn++) {
            const int col = jn * 8 + 2 * (lane & 3);
            *(__half2*)(Ps + r0 * AHP + col) =
                __floats2half2_rn(of[im][jn][0] * inv[im][0],
                                  of[im][jn][1] * inv[im][0]);
            *(__half2*)(Ps + (r0 + 8) * AHP + col) =
                __floats2half2_rn(of[im][jn][2] * inv[im][1],
                                  of[im][jn][3] * inv[im][1]);
        }
    }
    __syncthreads();

#pragma unroll
    for (int j = 0; j < 8; j++) {
        int chunk = tid + j * 128;
        int row = chunk >> 3, seg = chunk & 7;
        uint4 v = *(uint4*)(Ps + row * AHP + seg * 8);
        *(uint4*)(g_attn + (size_t)(b * SEQ + tq0 + row) * NC + h * HD + seg * 8) = v;
    }

    __threadfence();
    __syncthreads();
    if (tid == 0) atomicAdd(&g_fB[b * 16 + bx], 1);
}

// ---------------------------------------------------------------------------
// Fused kernel (R9 schedule, 128 threads): 768 QKV | 512 attn | 256 proj.
// QKV pp-major; attn pp-major heavy-first; proj m-block ascending.
// ---------------------------------------------------------------------------
__global__ __launch_bounds__(128, 2) void fused(
    const float* __restrict__ qkv_b,
    const float* __restrict__ proj_b,
    float* __restrict__ out)
{
    extern __shared__ char smc[];
    const int bid = blockIdx.x;

    if (bid < 768) {
        // QKV: pp-major; within pair: (q,k,v) x m-blocks (batches interleaved)
        const int pp   = bid / 96;
        const int r    = bid % 96;
        const int kind = r % 3;
        const int mbs  = r / 3;
        const int nb   = pp + kind * 8;
        const int mb   = (mbs >> 1) | ((mbs & 1) << 4);
        gemm_body<1>(smc, mb * 128, nb * 128, qkv_b, nullptr);
        __threadfence();
        __syncthreads();
        if (threadIdx.x == 0)
            atomicOr(&g_fA[nb * 2 + (mb >> 4)], 1u << (mb & 15));
    } else if (bid < 1280) {
        attn_body(smc, bid - 768);
    } else {
        const int c  = bid - 1280;
        const int mb = c >> 3;          // m-block ascending: early rows first
        const int nb = c & 7;
        if (threadIdx.x == 0) {
            while ((int)ldacq(&g_fB[mb]) < 16) __nanosleep(256);
        }
        __syncthreads();
        gemm_body<2>(smc, mb * 128, nb * 128, proj_b, out);
    }
}

// ---------------------------------------------------------------------------
// kernel_launch
// ---------------------------------------------------------------------------
extern "C" void kernel_launch(void* const* d_in, const int* in_sizes, int n_in,
                              void* d_out, int out_size)
{
    const float* x      = (const float*)d_in[0];
    const float* qkv_w  = (const float*)d_in[1];
    const float* qkv_b  = (const float*)d_in[2];
    const float* proj_w = (const float*)d_in[3];
    const float* proj_b = (const float*)d_in[4];
    float* out = (float*)d_out;

    cudaFuncSetAttribute(fused,
                         cudaFuncAttributeMaxDynamicSharedMemorySize, FUSED_SMEM);

    // 0) fp32 -> fp16 conversion + flag reset
    prep_all<<<1184, 256>>>((const float4*)x, (const float4*)qkv_w,
                            (const float4*)proj_w);

    // 1-3) Fused QKV + attention + projection (128-thread blocks, fat warps)
    fused<<<1536, 128, FUSED_SMEM>>>(qkv_b, proj_b, out);
}

// round 17
// speedup vs baseline: 1.0364x; 1.0128x over previous
#include <cuda_runtime.h>
#include <cuda_fp16.h>
#include <cstdint>
#include <cstddef>

// Problem constants
#define BATCH 2
#define SEQ   2048
#define NC    1024
#define NH    16
#define HD    64
#define MROWS (BATCH*SEQ)     // 4096
#define QKVN  (3*NC)          // 3072
#define GK    1024
// q scale folds softmax scale (1/8) and log2(e): logits land in log2 domain
#define QSCALE (0.125f * 1.4426950408889634f)

// Scratch (allocation-free rule: __device__ globals), all fp16
__device__ __half g_q[BATCH*NH*SEQ*HD];     // [b,h,t,d], pre-scaled by QSCALE
__device__ __half g_k[BATCH*NH*SEQ*HD];
__device__ __half g_v[BATCH*NH*SEQ*HD];
__device__ __half g_attn[BATCH*SEQ*NC];     // [b,t,c]
__device__ __half g_x[MROWS*GK];
__device__ __half g_w1[QKVN*GK];
__device__ __half g_w2[NC*GK];

// Dependency flags (zeroed by prep_all each launch)
__device__ uint32_t g_fA[48];   // [nb][b]: bitmask of finished QKV m-blocks
__device__ int      g_fB[32];   // [b*16+bx]: count of finished attn head-blocks

__device__ __forceinline__ uint32_t h2u(__half2 h) {
    return *reinterpret_cast<uint32_t*>(&h);
}
__device__ __forceinline__ float ex2f(float x) {
    float y;
    asm("ex2.approx.ftz.f32 %0, %1;" : "=f"(y) : "f"(x));
    return y;
}
__device__ __forceinline__ uint32_t ldacq(const void* p) {
    uint32_t v;
    asm volatile("ld.acquire.gpu.u32 %0, [%1];" : "=r"(v) : "l"(p) : "memory");
    return v;
}

#define CP16(dst_u32, src_ptr) \
    asm volatile("cp.async.cg.shared.global [%0], [%1], 16;" \
                 :: "r"(dst_u32), "l"(src_ptr) : "memory")
#define CP_COMMIT() asm volatile("cp.async.commit_group;" ::: "memory")
#define CP_WAIT(n)  asm volatile("cp.async.wait_group %0;" :: "n"(n) : "memory")

__device__ __forceinline__ void ldsm4(uint32_t* r, uint32_t a) {
    asm volatile("ldmatrix.sync.aligned.m8n8.x4.shared.b16 {%0,%1,%2,%3}, [%4];"
                 : "=r"(r[0]), "=r"(r[1]), "=r"(r[2]), "=r"(r[3]) : "r"(a));
}
__device__ __forceinline__ void ldsm4t(uint32_t* r, uint32_t a) {
    asm volatile("ldmatrix.sync.aligned.m8n8.x4.trans.shared.b16 {%0,%1,%2,%3}, [%4];"
                 : "=r"(r[0]), "=r"(r[1]), "=r"(r[2]), "=r"(r[3]) : "r"(a));
}
__device__ __forceinline__ void mma16816(float* d, const uint32_t* a,
                                         uint32_t b0, uint32_t b1) {
    asm volatile("mma.sync.aligned.m16n8k16.row.col.f32.f16.f16.f32 "
                 "{%0,%1,%2,%3}, {%4,%5,%6,%7}, {%8,%9}, {%0,%1,%2,%3};"
                 : "+f"(d[0]), "+f"(d[1]), "+f"(d[2]), "+f"(d[3])
                 : "r"(a[0]), "r"(a[1]), "r"(a[2]), "r"(a[3]),
                   "r"(b0), "r"(b1));
}

// ---------------------------------------------------------------------------
// prep: fp32 -> fp16 for x, qkv_w, proj_w; also zero dependency flags.
// ---------------------------------------------------------------------------
#define N8X  (MROWS*GK/8)     // 524288
#define N8W1 (QKVN*GK/8)      // 393216
#define N8W2 (NC*GK/8)        // 131072
__global__ void prep_all(const float4* __restrict__ x,
                         const float4* __restrict__ w1,
                         const float4* __restrict__ w2)
{
    if (blockIdx.x == 0 && threadIdx.x < 80) {
        if (threadIdx.x < 48) g_fA[threadIdx.x] = 0;
        else                  g_fB[threadIdx.x - 48] = 0;
    }
    uint4* dx  = (uint4*)g_x;
    uint4* dw1 = (uint4*)g_w1;
    uint4* dw2 = (uint4*)g_w2;
    for (int i = blockIdx.x * blockDim.x + threadIdx.x;
         i < N8X + N8W1 + N8W2; i += gridDim.x * blockDim.x) {
        const float4* s;
        uint4* d;
        int j;
        if (i < N8X)               { s = x;  d = dx;  j = i; }
        else if (i < N8X + N8W1)   { s = w1; d = dw1; j = i - N8X; }
        else                       { s = w2; d = dw2; j = i - N8X - N8W1; }
        float4 a = s[2 * j], b = s[2 * j + 1];
        uint4 o;
        o.x = h2u(__floats2half2_rn(a.x, a.y));
        o.y = h2u(__floats2half2_rn(a.z, a.w));
        o.z = h2u(__floats2half2_rn(b.x, b.y));
        o.w = h2u(__floats2half2_rn(b.z, b.w));
        d[j] = o;
    }
}

// ---------------------------------------------------------------------------
// GEMM body, 128 threads: 128x128 tile, 4 warps in 2x2, warp tile 64x64.
// K-chunk 64 (halved barrier count), 3-stage cp.async pipeline.
// Row layout: 128B per row = two 64B k-halves, each with the proven
// seg^=(row>>1)&3 swizzle -> conflict-free ldmatrix.
// EPI 1: A=g_x, W=g_w1, scatter q/k/v fp16 (q scaled by QSCALE)
// EPI 2: A=g_attn, W=g_w2, fp32 store + bias
// ---------------------------------------------------------------------------
#define KCH   64
#define STGB  32768                 // stage bytes: A 16K + B 16K
#define CPCH  132
#define FUSED_SMEM 98304            // 3 stages x 32KB

template<int EPI>
__device__ __forceinline__ void gemm_body(char* smc, int m0, int n0,
                                          const float* __restrict__ bias,
                                          float* __restrict__ C)
{
    float* Cs = (float*)smc;
    const uint32_t sbase = (uint32_t)__cvta_generic_to_shared(smc);

    const __half* __restrict__ A = (EPI == 1) ? g_x  : g_attn;
    const __half* __restrict__ W = (EPI == 1) ? g_w1 : g_w2;
    const int N = (EPI == 1) ? QKVN : NC;

    const int tid  = threadIdx.x;
    const int lane = tid & 31;
    const int wid  = tid >> 5;        // 0..3
    const int wm = wid >> 1;          // 0..1 (64-row slab)
    const int wn = wid & 1;           // 0..1 (64-col slab)

    float acc[4][8][4];               // [im][jn(8 x n8)][c]
#pragma unroll
    for (int im = 0; im < 4; im++)
#pragma unroll
        for (int jn = 0; jn < 8; jn++)
#pragma unroll
            for (int c = 0; c < 4; c++) acc[im][jn][c] = 0.f;

    // 2048 16B chunks per stage: idx<1024 -> A (r=idx>>3, s=idx&7), else W.
    // smem addr: r*128 + (s>>2)*64 + ((s&3)^((r>>1)&3))*16
#define GISSUE(ch) do {                                                       \
        uint32_t _st = sbase + (uint32_t)(((ch) % 3) * STGB);                 \
        int _k0 = (ch) * KCH;                                                 \
        _Pragma("unroll")                                                     \
        for (int _j = 0; _j < 16; _j++) {                                     \
            int _idx = tid + _j * 128;                                        \
            int _r = (_idx & 1023) >> 3, _s = _idx & 7;                       \
            int _p = (_s & 3) ^ ((_r >> 1) & 3);                              \
            uint32_t _off = (uint32_t)(_r * 128 + (_s >> 2) * 64 + _p * 16);  \
            if (_idx < 1024)                                                  \
                CP16(_st + _off,                                              \
                     A + (size_t)(m0 + _r) * GK + _k0 + _s * 8);              \
            else                                                              \
                CP16(_st + 16384u + _off,                                     \
                     W + (size_t)(n0 + _r) * GK + _k0 + _s * 8);              \
        }                                                                     \
    } while (0)

    GISSUE(0); CP_COMMIT();
    GISSUE(1); CP_COMMIT();

    const int lr = lane & 15;
    const int lh = lane >> 4;

    constexpr int NCH = GK / KCH;     // 16
    for (int i = 0; i < NCH; i++) {
        CP_WAIT(1);
        __syncthreads();
        if (i + 2 < NCH) GISSUE(i + 2);
        CP_COMMIT();

        const uint32_t ab = sbase + (uint32_t)((i % 3) * STGB);
        const uint32_t bb = ab + 16384u;

#pragma unroll
        for (int dk = 0; dk < 4; dk++) {
            const int khalf = dk >> 1;
            const int iseg  = (dk & 1) * 2 + lh;
            uint32_t bf[4][4];
#pragma unroll
            for (int jn2 = 0; jn2 < 4; jn2++) {
                int row = wn * 64 + jn2 * 16 + lr;
                int p = iseg ^ ((row >> 1) & 3);
                ldsm4(bf[jn2], bb + (uint32_t)(row * 128 + khalf * 64 + p * 16));
            }
#pragma unroll
            for (int im = 0; im < 4; im++) {
                uint32_t af[4];
                int row = wm * 64 + im * 16 + lr;
                int p = iseg ^ ((row >> 1) & 3);
                ldsm4(af, ab + (uint32_t)(row * 128 + khalf * 64 + p * 16));
                // B frag order: [0]=(n0-7,k0-7) [1]=(n8-15,k0-7)
                //               [2]=(n0-7,k8-15) [3]=(n8-15,k8-15)
#pragma unroll
                for (int jn2 = 0; jn2 < 4; jn2++) {
                    mma16816(acc[im][jn2 * 2 + 0], af, bf[jn2][0], bf[jn2][2]);
                    mma16816(acc[im][jn2 * 2 + 1], af, bf[jn2][1], bf[jn2][3]);
                }
            }
        }
    }
#undef GISSUE
    __syncthreads();

    // Epilogue: acc frags -> smem (fp32, m16n8 layout) -> bias/scatter
    const int rsub = lane >> 2;
    const int csub = 2 * (lane & 3);
#pragma unroll
    for (int im = 0; im < 4; im++) {
        const int r0 = wm * 64 + im * 16 + rsub;
#pragma unroll
        for (int jn = 0; jn < 8; jn++) {
            const int c0 = wn * 64 + jn * 8 + csub;
            *(float2*)(Cs + r0 * CPCH + c0) =
                make_float2(acc[im][jn][0], acc[im][jn][1]);
            *(float2*)(Cs + (r0 + 8) * CPCH + c0) =
                make_float2(acc[im][jn][2], acc[im][jn][3]);
        }
    }
    __syncthreads();

#pragma unroll
    for (int l = 0; l < 32; l++) {
        int idx = tid + l * 128;
        int row = idx >> 5;
        int col = (idx & 31) * 4;
        float4 v  = *(float4*)(Cs + row * CPCH + col);
        float4 bb = *(const float4*)(bias + n0 + col);
        v.x += bb.x; v.y += bb.y; v.z += bb.z; v.w += bb.w;
        int m = m0 + row;
        if (EPI == 1) {
            int n = n0 + col;
            int kind = n >> 10;
            int c = n & 1023;
            int h = c >> 6;
            int d = c & 63;
            if (kind == 0) {
                v.x *= QSCALE; v.y *= QSCALE; v.z *= QSCALE; v.w *= QSCALE;
            }
            __half* buf = (kind == 0) ? g_q : (kind == 1) ? g_k : g_v;
            int b = m >> 11;
            int t = m & 2047;
            uint2 u;
            u.x = h2u(__floats2half2_rn(v.x, v.y));
            u.y = h2u(__floats2half2_rn(v.z, v.w));
            *(uint2*)(buf + ((size_t)((b * NH + h) * SEQ + t)) * HD + d) = u;
        } else {
            *(float4*)(C + (size_t)m * N + n0 + col) = v;
        }
    }
}

// ---------------------------------------------------------------------------
// Attention body (R16-proven): 128 threads, 4 warps (warp = 32 q-rows),
// q-tile 128, kv-tile 64, double-buffered cp.async. Register-resident S->P,
// no max-subtraction, ex2 in log2 domain. Flags as in R9.
// ---------------------------------------------------------------------------
#define AHP    72
#define KVSTG  18432
#define OFF_KV 18432

__device__ __forceinline__ void attn_body(char* smc, int a)
{
    __half* Ps = (__half*)smc;
    const uint32_t sbase = (uint32_t)__cvta_generic_to_shared(smc);

    const int tid  = threadIdx.x;
    const int lane = tid & 31;
    const int wid  = tid >> 5;

    const int pp = a >> 6;             // head pair 0..7
    const int s  = a & 63;             // heavy-first within pair
    const int bx = 15 - (s >> 2);
    const int b  = s & 1;
    const int h  = pp * 2 + ((s >> 1) & 1);
    const int bh = b * 16 + h;
    const int tq0 = bx * 128;
    const int ntiles = 2 * bx + 2;

    // Wait for q tile bx and full k/v prefix of this (head, batch).
    if (tid == 0) {
        const uint32_t need = (1u << (bx + 1)) - 1u;
        while (true) {
            uint32_t fq = ldacq(&g_fA[pp * 2 + b]);
            uint32_t fk = ldacq(&g_fA[(8 + pp) * 2 + b]);
            uint32_t fv = ldacq(&g_fA[(16 + pp) * 2 + b]);
            if (((fq >> bx) & 1u) && (fk & need) == need && (fv & need) == need)
                break;
            __nanosleep(128);
        }
    }
    __syncthreads();

    const __half* Qg = g_q + (size_t)bh * SEQ * HD;
    const __half* Kg = g_k + (size_t)bh * SEQ * HD;
    const __half* Vg = g_v + (size_t)bh * SEQ * HD;

    // Q: 128 rows x 8 chunks of 16B
#pragma unroll
    for (int j = 0; j < 8; j++) {
        int idx = tid + j * 128;
        int r = idx >> 3, g = idx & 7;
        CP16(sbase + (uint32_t)((r * AHP + g * 8) * 2),
             Qg + (size_t)(tq0 + r) * HD + g * 8);
    }
#define ISSUE_KV(tile) do {                                                   \
        int _s = (tile) & 1;                                                  \
        int _k0 = (tile) * 64;                                                \
        uint32_t _kb = sbase + OFF_KV + (uint32_t)_s * KVSTG;                 \
        _Pragma("unroll")                                                     \
        for (int _j = 0; _j < 4; _j++) {                                      \
            int _idx = tid + _j * 128;                                        \
            int _r = _idx >> 3, _g = _idx & 7;                                \
            CP16(_kb + (uint32_t)((_r * AHP + _g * 8) * 2),                   \
                 Kg + (size_t)(_k0 + _r) * HD + _g * 8);                      \
            CP16(_kb + 9216u + (uint32_t)((_r * AHP + _g * 8) * 2),           \
                 Vg + (size_t)(_k0 + _r) * HD + _g * 8);                      \
        }                                                                     \
    } while (0)

    ISSUE_KV(0); CP_COMMIT();      // group 0: Q + KV0
    ISSUE_KV(1); CP_COMMIT();

    uint32_t qf[2][4][4];          // [im][dk] A-frags, persistent
    float of[2][8][4];             // [im][jn] O accumulators
    float rs[2][2] = {{0.f, 0.f}, {0.f, 0.f}};
#pragma unroll
    for (int im = 0; im < 2; im++)
#pragma unroll
        for (int jn = 0; jn < 8; jn++)
#pragma unroll
            for (int c = 0; c < 4; c++) of[im][jn][c] = 0.f;

    const int g8  = lane >> 3;      // ldmatrix address group
    const int li  = lane & 7;
    const int rsub = lane >> 2;     // acc row within 16-block

    for (int i = 0; i < ntiles; i++) {
        CP_WAIT(1);
        __syncthreads();
        const uint32_t kb = sbase + OFF_KV + (uint32_t)(i & 1) * KVSTG;
        const uint32_t vb = kb + 9216u;

        if (i == 0) {
#pragma unroll
            for (int im = 0; im < 2; im++)
#pragma unroll
                for (int dk = 0; dk < 4; dk++) {
                    uint32_t qa = sbase + (uint32_t)(((wid * 32 + im * 16 + (lane & 15)) * AHP
                                   + dk * 16 + (lane >> 4) * 8) * 2);
                    ldsm4(qf[im][dk], qa);
                }
        }

        const int kt0 = i * 64;
        const bool msk = (i >= ntiles - 2);
        uint32_t pa[2][4][4];       // P as A-frags: [im][kk]

#pragma unroll
        for (int jnp = 0; jnp < 4; jnp++) {
            float sc[2][2][4];
#pragma unroll
            for (int im = 0; im < 2; im++)
#pragma unroll
                for (int jh = 0; jh < 2; jh++)
#pragma unroll
                    for (int c = 0; c < 4; c++) sc[im][jh][c] = 0.f;

#pragma unroll
            for (int dk = 0; dk < 4; dk++) {
                uint32_t kf[4];
                // groups: n-block = g8>>1, k-block = g8&1
                uint32_t ka = kb + (uint32_t)(((jnp * 16 + (g8 >> 1) * 8 + li) * AHP
                               + dk * 16 + (g8 & 1) * 8) * 2);
                ldsm4(kf, ka);
                mma16816(sc[0][0], qf[0][dk], kf[0], kf[1]);
                mma16816(sc[0][1], qf[0][dk], kf[2], kf[3]);
                mma16816(sc[1][0], qf[1][dk], kf[0], kf[1]);
                mma16816(sc[1][1], qf[1][dk], kf[2], kf[3]);
            }
            // exp2 + mask + pack to fp16 A-frags + row sums (all in regs)
#pragma unroll
            for (int im = 0; im < 2; im++) {
                const int rr0 = tq0 + wid * 32 + im * 16 + rsub;
                const int rr1 = rr0 + 8;
#pragma unroll
                for (int jh = 0; jh < 2; jh++) {
                    const int cb = kt0 + jnp * 16 + jh * 8 + 2 * (lane & 3);
                    float p0 = ex2f(sc[im][jh][0]);
                    float p1 = ex2f(sc[im][jh][1]);
                    float p2 = ex2f(sc[im][jh][2]);
                    float p3 = ex2f(sc[im][jh][3]);
                    if (msk) {
                        if (cb     > rr0) p0 = 0.f;
                        if (cb + 1 > rr0) p1 = 0.f;
                        if (cb     > rr1) p2 = 0.f;
                        if (cb + 1 > rr1) p3 = 0.f;
                    }
                    rs[im][0] += p0 + p1;
                    rs[im][1] += p2 + p3;
                    pa[im][jnp][jh * 2 + 0] = h2u(__floats2half2_rn(p0, p1));
                    pa[im][jnp][jh * 2 + 1] = h2u(__floats2half2_rn(p2, p3));
                }
            }
        }

        // O += P V
#pragma unroll
        for (int kk = 0; kk < 4; kk++) {
#pragma unroll
            for (int j2 = 0; j2 < 4; j2++) {
                uint32_t vf[4];
                // groups: k-block = g8&1, n-block = g8>>1 (trans load)
                uint32_t va = vb + (uint32_t)(((kk * 16 + (g8 & 1) * 8 + li) * AHP
                               + j2 * 16 + (g8 >> 1) * 8) * 2);
                ldsm4t(vf, va);
                mma16816(of[0][2 * j2],     pa[0][kk], vf[0], vf[1]);
                mma16816(of[1][2 * j2],     pa[1][kk], vf[0], vf[1]);
                mma16816(of[0][2 * j2 + 1], pa[0][kk], vf[2], vf[3]);
                mma16816(of[1][2 * j2 + 1], pa[1][kk], vf[2], vf[3]);
            }
        }
        __syncthreads();
        if (i + 2 < ntiles) ISSUE_KV(i + 2);
        CP_COMMIT();
    }
#undef ISSUE_KV

    // Row-sum reduce across the 4 lanes sharing each row, invert.
    float inv[2][2];
#pragma unroll
    for (int im = 0; im < 2; im++)
#pragma unroll
        for (int jr = 0; jr < 2; jr++) {
            float v = rs[im][jr];
            v += __shfl_xor_sync(0xffffffff, v, 1);
            v += __shfl_xor_sync(0xffffffff, v, 2);
            inv[im][jr] = 1.0f / v;
        }

    // Normalize + stage O to smem (fp16), then coalesced copy to g_attn.
#pragma unroll
    for (int im = 0; im < 2; im++) {
        const int r0 = wid * 32 + im * 16 + rsub;
#pragma unroll
        for (int jn = 0; jn < 8; jn++) {
            const int col = jn * 8 + 2 * (lane & 3);
            *(__half2*)(Ps + r0 * AHP + col) =
                __floats2half2_rn(of[im][jn][0] * inv[im][0],
                                  of[im][jn][1] * inv[im][0]);
            *(__half2*)(Ps + (r0 + 8) * AHP + col) =
                __floats2half2_rn(of[im][jn][2] * inv[im][1],
                                  of[im][jn][3] * inv[im][1]);
        }
    }
    __syncthreads();

#pragma unroll
    for (int j = 0; j < 8; j++) {
        int chunk = tid + j * 128;
        int row = chunk >> 3, seg = chunk & 7;
        uint4 v = *(uint4*)(Ps + row * AHP + seg * 8);
        *(uint4*)(g_attn + (size_t)(b * SEQ + tq0 + row) * NC + h * HD + seg * 8) = v;
    }

    __threadfence();
    __syncthreads();
    if (tid == 0) atomicAdd(&g_fB[b * 16 + bx], 1);
}

// ---------------------------------------------------------------------------
// Fused kernel (R9 schedule, 128 threads): 768 QKV | 512 attn | 256 proj.
// QKV pp-major; attn pp-major heavy-first; proj m-block ascending.
// ---------------------------------------------------------------------------
__global__ __launch_bounds__(128, 2) void fused(
    const float* __restrict__ qkv_b,
    const float* __restrict__ proj_b,
    float* __restrict__ out)
{
    extern __shared__ char smc[];
    const int bid = blockIdx.x;

    if (bid < 768) {
        // QKV: pp-major; within pair: (q,k,v) x m-blocks (batches interleaved)
        const int pp   = bid / 96;
        const int r    = bid % 96;
        const int kind = r % 3;
        const int mbs  = r / 3;
        const int nb   = pp + kind * 8;
        const int mb   = (mbs >> 1) | ((mbs & 1) << 4);
        gemm_body<1>(smc, mb * 128, nb * 128, qkv_b, nullptr);
        __threadfence();
        __syncthreads();
        if (threadIdx.x == 0)
            atomicOr(&g_fA[nb * 2 + (mb >> 4)], 1u << (mb & 15));
    } else if (bid < 1280) {
        attn_body(smc, bid - 768);
    } else {
        const int c  = bid - 1280;
        const int mb = c >> 3;          // m-block ascending: early rows first
        const int nb = c & 7;
        if (threadIdx.x == 0) {
            while ((int)ldacq(&g_fB[mb]) < 16) __nanosleep(256);
        }
        __syncthreads();
        gemm_body<2>(smc, mb * 128, nb * 128, proj_b, out);
    }
}

// ---------------------------------------------------------------------------
// kernel_launch
// ---------------------------------------------------------------------------
extern "C" void kernel_launch(void* const* d_in, const int* in_sizes, int n_in,
                              void* d_out, int out_size)
{
    const float* x      = (const float*)d_in[0];
    const float* qkv_w  = (const float*)d_in[1];
    const float* qkv_b  = (const float*)d_in[2];
    const float* proj_w = (const float*)d_in[3];
    const float* proj_b = (const float*)d_in[4];
    float* out = (float*)d_out;

    cudaFuncSetAttribute(fused,
                         cudaFuncAttributeMaxDynamicSharedMemorySize, FUSED_SMEM);

    // 0) fp32 -> fp16 conversion + flag reset
    prep_all<<<1184, 256>>>((const float4*)x, (const float4*)qkv_w,
                            (const float4*)proj_w);

    // 1-3) Fused QKV + attention + projection (K-chunk 64, 3-stage)
    fused<<<1536, 128, FUSED_SMEM>>>(qkv_b, proj_b, out);
}